// round 16
// baseline (speedup 1.0000x reference)
#include <cuda_runtime.h>
#include <cuda_bf16.h>
#include <math.h>
#include <stdint.h>

// ---------------- problem constants ----------------
#define NTOK 8192
#define DDIM 2048
#define HDIM 1024
#define NEXP 8
#define SHDIM 2048
#define CAP  17408   // 16384 slots + 8*128 pad headroom

#define DH   (DDIM * HDIM)
#define SW   (DDIM * SHDIM)

// ---------------- scratch (device globals) ----------------
__device__ int   g_count[NEXP];
__device__ int   g_cursor[NEXP];
__device__ int   g_pbase[NEXP + 1];
__device__ int   g_tok_eid[NTOK * 2];
__device__ float g_tok_gate[NTOK * 2];
__device__ int   g_tok_slot[NTOK * 2];
__device__ int   g_slot_tok[CAP];
__device__ float g_slot_gate[CAP];

// bf16 hi/lo planes (hi first, lo second)
__device__ __align__(16) __nv_bfloat16 g_A1[2ull * CAP * DDIM];
__device__ __align__(16) __nv_bfloat16 g_xs[2ull * NTOK * DDIM];
__device__ __align__(16) __nv_bfloat16 g_w1s[2ull * NEXP * DH];
__device__ __align__(16) __nv_bfloat16 g_w2s[2ull * NEXP * DH];
__device__ __align__(16) __nv_bfloat16 g_sw1s[2ull * SW];
__device__ __align__(16) __nv_bfloat16 g_sw2s[2ull * SW];
__device__ __align__(16) __nv_bfloat16 g_h[2ull * CAP * HDIM];
__device__ __align__(16) __nv_bfloat16 g_hs[2ull * NTOK * SHDIM];

// ---------------- helpers ----------------
__device__ __forceinline__ uint32_t smem_u32(const void* p) {
    uint32_t a;
    asm("{ .reg .u64 t; cvta.to.shared.u64 t, %1; cvt.u32.u64 %0, t; }" : "=r"(a) : "l"(p));
    return a;
}
__device__ __forceinline__ void cpa16(uint32_t dst, const void* src) {
    asm volatile("cp.async.cg.shared.global [%0], [%1], 16;" :: "r"(dst), "l"(src));
}
#define CP_COMMIT() asm volatile("cp.async.commit_group;" ::: "memory")
#define CP_WAIT1()  asm volatile("cp.async.wait_group 1;" ::: "memory")
#define CP_WAIT0()  asm volatile("cp.async.wait_group 0;" ::: "memory")

__device__ __forceinline__ void ldsm4(uint32_t* r, uint32_t addr) {
    asm volatile("ldmatrix.sync.aligned.m8n8.x4.shared.b16 {%0,%1,%2,%3}, [%4];"
                 : "=r"(r[0]), "=r"(r[1]), "=r"(r[2]), "=r"(r[3]) : "r"(addr));
}
__device__ __forceinline__ void ldsm4t(uint32_t* r, uint32_t addr) {
    asm volatile("ldmatrix.sync.aligned.m8n8.x4.trans.shared.b16 {%0,%1,%2,%3}, [%4];"
                 : "=r"(r[0]), "=r"(r[1]), "=r"(r[2]), "=r"(r[3]) : "r"(addr));
}
__device__ __forceinline__ void mma16816(float* c, const uint32_t* a, const uint32_t* b) {
    asm volatile(
        "mma.sync.aligned.m16n8k16.row.col.f32.bf16.bf16.f32 "
        "{%0,%1,%2,%3}, {%4,%5,%6,%7}, {%8,%9}, {%0,%1,%2,%3};"
        : "+f"(c[0]), "+f"(c[1]), "+f"(c[2]), "+f"(c[3])
        : "r"(a[0]), "r"(a[1]), "r"(a[2]), "r"(a[3]), "r"(b[0]), "r"(b[1]));
}
__device__ __forceinline__ float gelu_exact(float v) {
    return 0.5f * v * (1.0f + erff(v * 0.70710678118654752f));
}
__device__ __forceinline__ uint32_t bf2u(__nv_bfloat16 a, __nv_bfloat16 b) {
    return (uint32_t)__bfloat16_as_ushort(a) | ((uint32_t)__bfloat16_as_ushort(b) << 16);
}
__device__ __forceinline__ void split4(float4 v, uint2& hi, uint2& lo) {
    __nv_bfloat16 h0 = __float2bfloat16(v.x), h1 = __float2bfloat16(v.y);
    __nv_bfloat16 h2 = __float2bfloat16(v.z), h3 = __float2bfloat16(v.w);
    __nv_bfloat16 l0 = __float2bfloat16(v.x - __bfloat162float(h0));
    __nv_bfloat16 l1 = __float2bfloat16(v.y - __bfloat162float(h1));
    __nv_bfloat16 l2 = __float2bfloat16(v.z - __bfloat162float(h2));
    __nv_bfloat16 l3 = __float2bfloat16(v.w - __bfloat162float(h3));
    hi = make_uint2(bf2u(h0, h1), bf2u(h2, h3));
    lo = make_uint2(bf2u(l0, l1), bf2u(l2, l3));
}

// ============================================================
// gating v2 (smem-cached gw), no global atomics
// ============================================================
#define GATE_SMEM (DDIM * 9 * 4)

extern __shared__ __align__(16) char smem[];

__global__ void __launch_bounds__(256, 2)
k_gate(const float* __restrict__ x, const float* __restrict__ gw) {
    float* gws = (float*)smem;
    for (int i = threadIdx.x; i < DDIM * 8; i += 256) {
        int d = i >> 3, e = i & 7;
        gws[d * 9 + e] = gw[i];
    }
    __syncthreads();

    int warp = threadIdx.x >> 5, lane = threadIdx.x & 31;
    int tok = blockIdx.x * 8 + warp;
    const float* xr = x + (size_t)tok * DDIM;
    float acc[8] = {0.f,0.f,0.f,0.f,0.f,0.f,0.f,0.f};
    for (int d = lane; d < DDIM; d += 32) {
        float xv = xr[d];
        const float* g = gws + d * 9;
        acc[0] += xv * g[0]; acc[1] += xv * g[1]; acc[2] += xv * g[2]; acc[3] += xv * g[3];
        acc[4] += xv * g[4]; acc[5] += xv * g[5]; acc[6] += xv * g[6]; acc[7] += xv * g[7];
    }
#pragma unroll
    for (int e = 0; e < 8; e++)
#pragma unroll
        for (int o = 16; o; o >>= 1) acc[e] += __shfl_xor_sync(0xffffffffu, acc[e], o);
    if (lane == 0) {
        int e0 = 0; float l0 = acc[0];
#pragma unroll
        for (int e = 1; e < 8; e++) if (acc[e] > l0) { l0 = acc[e]; e0 = e; }
        int e1 = -1; float l1 = -3.4e38f;
#pragma unroll
        for (int e = 0; e < 8; e++) if (e != e0 && acc[e] > l1) { l1 = acc[e]; e1 = e; }
        float ex = expf(l1 - l0);
        float inv = 1.f / (1.f + ex);
        g_tok_eid[tok*2+0] = e0;  g_tok_eid[tok*2+1] = e1;
        g_tok_gate[tok*2+0] = inv; g_tok_gate[tok*2+1] = ex * inv;
    }
}

__global__ void k_zero_out(float4* __restrict__ out) {
    size_t i = (size_t)blockIdx.x * 256 + threadIdx.x;
    out[i] = make_float4(0.f, 0.f, 0.f, 0.f);
}

__global__ void k_scan() {
    __shared__ int cnt[NEXP];
    __shared__ int sbase[NEXP + 1];
    if (threadIdx.x < NEXP) cnt[threadIdx.x] = 0;
    __syncthreads();
    for (int i = threadIdx.x; i < NTOK * 2; i += 256)
        atomicAdd(&cnt[g_tok_eid[i]], 1);
    __syncthreads();
    if (threadIdx.x == 0) {
        int base = 0;
        for (int e = 0; e < NEXP; e++) {
            g_count[e] = cnt[e];
            g_pbase[e] = base; g_cursor[e] = base; sbase[e] = base;
            base += (cnt[e] + 127) & ~127;
        }
        g_pbase[NEXP] = base; sbase[NEXP] = base;
    }
    __syncthreads();
    for (int e = 0; e < NEXP; e++) {
        int cs = sbase[e] + cnt[e];
        int ce = sbase[e + 1];
        for (int s = cs + threadIdx.x; s < ce; s += blockDim.x) {
            g_slot_tok[s] = 0; g_slot_gate[s] = 0.f;
        }
    }
}

__global__ void k_scatter() {
    int tok = blockIdx.x * 256 + threadIdx.x;
#pragma unroll
    for (int k = 0; k < 2; k++) {
        int e = g_tok_eid[tok*2+k];
        int pos = atomicAdd(&g_cursor[e], 1);
        g_slot_tok[pos] = tok;
        g_slot_gate[pos] = g_tok_gate[tok*2+k];
        g_tok_slot[tok*2+k] = pos;
    }
}

#define N1 (NEXP * DH / 4)
#define N2 (SW / 4)
__global__ void k_split_w(const float4* __restrict__ w1, const float4* __restrict__ w2,
                          const float4* __restrict__ sw1, const float4* __restrict__ sw2,
                          __nv_bfloat16* __restrict__ w1s, __nv_bfloat16* __restrict__ w2s,
                          __nv_bfloat16* __restrict__ sw1s, __nv_bfloat16* __restrict__ sw2s) {
    long long i = (long long)blockIdx.x * 256 + threadIdx.x;
    const float4* src; __nv_bfloat16 *dh, *dl; long long j;
    if (i < N1)                { j = i;               src = w1;  dh = w1s;  dl = w1s  + (size_t)NEXP * DH; }
    else if (i < 2LL * N1)     { j = i - N1;          src = w2;  dh = w2s;  dl = w2s  + (size_t)NEXP * DH; }
    else if (i < 2LL*N1 + N2)  { j = i - 2LL*N1;      src = sw1; dh = sw1s; dl = sw1s + (size_t)SW; }
    else                       { j = i - 2LL*N1 - N2; src = sw2; dh = sw2s; dl = sw2s + (size_t)SW; }
    uint2 hi, lo; split4(src[j], hi, lo);
    *(uint2*)(dh + j * 4) = hi;
    *(uint2*)(dl + j * 4) = lo;
}

// x -> g_xs planes (input-only; branch B)
__global__ void k_split_x(const float* __restrict__ x) {
    size_t i = (size_t)blockIdx.x * 256 + threadIdx.x;
    uint2 hi, lo; split4(((const float4*)x)[i], hi, lo);
    *(uint2*)(g_xs + i * 4) = hi;
    *(uint2*)(g_xs + (size_t)NTOK * DDIM + i * 4) = lo;
}

// gather split x rows into both g_A1 slots (branch A, after scatter)
__global__ void k_gather(const float* __restrict__ x) {
    int tok = blockIdx.x;
    int s0 = g_tok_slot[tok * 2], s1 = g_tok_slot[tok * 2 + 1];
    const float4* src = (const float4*)(x + (size_t)tok * DDIM);
#pragma unroll
    for (int i = 0; i < 2; i++) {
        int idx = threadIdx.x + i * 256;
        uint2 hi, lo; split4(src[idx], hi, lo);
        size_t o0 = (size_t)s0 * DDIM + idx * 4;
        size_t o1 = (size_t)s1 * DDIM + idx * 4;
        *(uint2*)(g_A1 + o0) = hi;
        *(uint2*)(g_A1 + (size_t)CAP * DDIM + o0) = lo;
        *(uint2*)(g_A1 + o1) = hi;
        *(uint2*)(g_A1 + (size_t)CAP * DDIM + o1) = lo;
    }
}

// ============================================================
// HMMA GEMM (runtime op; per-op grids launched on two streams)
// op0: routed L1 -> g_h planes          op1: routed L2 -> atomic out
// op2: shared L1 -> g_hs planes         op3: shared L2 -> atomic out
// ============================================================
#define OAH 0
#define OAL 10240
#define OBH 20480
#define OBL 29184
#define STG 37888
#define SMEM_SZ (3 * STG)

__global__ void __launch_bounds__(256, 2)
k_mma(int op, int nbx, const float* __restrict__ bias, float* __restrict__ oout)
{
    const int tid = threadIdx.x, wid = tid >> 5, lane = tid & 31;
    const int mb = blockIdx.x / nbx, nb = blockIdx.x % nbx;
    const int row_base = mb * 128;
    const int n0 = nb * 128;

    int K, ldA, ldB, ldO;
    int e = 0;
    if (op == 0 || op == 1) {
        if (row_base >= g_pbase[NEXP]) return;
        while (row_base >= g_pbase[e + 1]) e++;
    }
    const __nv_bfloat16 *Agh, *Agl, *Bgh, *Bgl;
    if (op == 0)      { K = DDIM; ldA = DDIM; ldB = HDIM; ldO = HDIM; bias += (size_t)e * HDIM;
                        Agh = g_A1;  Agl = Agh + (size_t)CAP * DDIM;
                        Bgh = g_w1s + (size_t)e * DH; Bgl = Bgh + (size_t)NEXP * DH; }
    else if (op == 1) { K = HDIM; ldA = HDIM; ldB = DDIM; ldO = DDIM; bias += (size_t)e * DDIM;
                        Agh = g_h;   Agl = Agh + (size_t)CAP * HDIM;
                        Bgh = g_w2s + (size_t)e * DH; Bgl = Bgh + (size_t)NEXP * DH; }
    else if (op == 2) { K = DDIM; ldA = DDIM; ldB = SHDIM; ldO = SHDIM;
                        Agh = g_xs;  Agl = Agh + (size_t)NTOK * DDIM;
                        Bgh = g_sw1s; Bgl = Bgh + (size_t)SW; }
    else              { K = SHDIM; ldA = SHDIM; ldB = DDIM; ldO = DDIM;
                        Agh = g_hs;  Agl = Agh + (size_t)NTOK * SHDIM;
                        Bgh = g_sw2s; Bgl = Bgh + (size_t)SW; }
    Agh += (size_t)row_base * ldA;
    Agl += (size_t)row_base * ldA;

    const uint32_t sb = smem_u32(smem);

    const int ar = tid >> 2, ac = (tid & 3) * 8;
    const int br = tid >> 4, bc = (tid & 15) * 8;

    auto load_stage = [&](int c, int st) {
        int kc = c << 5;
        uint32_t stb = sb + st * STG;
#pragma unroll
        for (int i = 0; i < 2; i++) {
            int row = ar + i * 64;
            uint32_t d = stb + (row * 40 + ac) * 2;
            cpa16(d + OAH, Agh + (size_t)row * ldA + kc + ac);
            cpa16(d + OAL, Agl + (size_t)row * ldA + kc + ac);
        }
#pragma unroll
        for (int i = 0; i < 2; i++) {
            int row = br + i * 16;
            uint32_t d = stb + (row * 136 + bc) * 2;
            cpa16(d + OBH, Bgh + (size_t)(kc + row) * ldB + n0 + bc);
            cpa16(d + OBL, Bgl + (size_t)(kc + row) * ldB + n0 + bc);
        }
        CP_COMMIT();
    };

    const int wm = (wid >> 2) * 64;
    const int wn = (wid & 3) * 32;
    const int lm = lane & 15, lh = lane >> 4;

    float acc[4][4][4] = {};

    const int nc = K >> 5;
    load_stage(0, 0);
    load_stage(1, 1);
    int st = 0;
    for (int c = 0; c < nc; c++) {
        if (c == nc - 1) { CP_WAIT0(); } else { CP_WAIT1(); }
        __syncthreads();

        uint32_t aAh = sb + st * STG + OAH;
        uint32_t aAl = sb + st * STG + OAL;
        uint32_t aBh = sb + st * STG + OBH;
        uint32_t aBl = sb + st * STG + OBL;
#pragma unroll
        for (int ks = 0; ks < 2; ks++) {
            int k0 = ks * 16;
            uint32_t af[4][4], bf[2][4], bf2[2][4];
#pragma unroll
            for (int mi = 0; mi < 4; mi++)
                ldsm4(af[mi], aAh + ((wm + mi * 16 + lm) * 40 + k0 + lh * 8) * 2);
#pragma unroll
            for (int np = 0; np < 2; np++)
                ldsm4t(bf[np], aBh + ((k0 + lm) * 136 + wn + np * 16 + lh * 8) * 2);
#pragma unroll
            for (int mi = 0; mi < 4; mi++)
#pragma unroll
                for (int ni = 0; ni < 4; ni++)
                    mma16816(acc[mi][ni], af[mi], &bf[ni >> 1][(ni & 1) * 2]);
#pragma unroll
            for (int np = 0; np < 2; np++)
                ldsm4t(bf2[np], aBl + ((k0 + lm) * 136 + wn + np * 16 + lh * 8) * 2);
#pragma unroll
            for (int mi = 0; mi < 4; mi++)
#pragma unroll
                for (int ni = 0; ni < 4; ni++)
                    mma16816(acc[mi][ni], af[mi], &bf2[ni >> 1][(ni & 1) * 2]);
#pragma unroll
            for (int mi = 0; mi < 4; mi++)
                ldsm4(af[mi], aAl + ((wm + mi * 16 + lm) * 40 + k0 + lh * 8) * 2);
#pragma unroll
            for (int mi = 0; mi < 4; mi++)
#pragma unroll
                for (int ni = 0; ni < 4; ni++)
                    mma16816(acc[mi][ni], af[mi], &bf[ni >> 1][(ni & 1) * 2]);
        }
        if (c + 2 < nc) load_stage(c + 2, st == 0 ? 2 : st - 1);
        st = (st == 2) ? 0 : st + 1;
    }

    // ---------------- epilogue ----------------
    __nv_bfloat16 *obh = 0, *obl = 0;
    if (op == 0)      { obh = g_h;  obl = g_h  + (size_t)CAP * HDIM; }
    else if (op == 2) { obh = g_hs; obl = g_hs + (size_t)NTOK * SHDIM; }

#pragma unroll
    for (int mi = 0; mi < 4; mi++) {
#pragma unroll
        for (int ni = 0; ni < 4; ni++) {
            int r = row_base + wm + mi * 16 + (lane >> 2);
            int col = n0 + wn + ni * 8 + (lane & 3) * 2;
            float b0 = bias[col], b1 = bias[col + 1];
#pragma unroll
            for (int half = 0; half < 2; half++) {
                int rr = r + half * 8;
                float v0 = acc[mi][ni][half * 2 + 0] + b0;
                float v1 = acc[mi][ni][half * 2 + 1] + b1;
                if (op == 0 || op == 2) {
                    size_t o = (size_t)rr * ldO + col;
                    v0 = gelu_exact(v0); v1 = gelu_exact(v1);
                    __nv_bfloat16 h0 = __float2bfloat16(v0);
                    __nv_bfloat16 h1 = __float2bfloat16(v1);
                    __nv_bfloat16 l0 = __float2bfloat16(v0 - __bfloat162float(h0));
                    __nv_bfloat16 l1 = __float2bfloat16(v1 - __bfloat162float(h1));
                    *(uint32_t*)(obh + o) = bf2u(h0, h1);
                    *(uint32_t*)(obl + o) = bf2u(l0, l1);
                } else if (op == 1) {
                    float g = g_slot_gate[rr];
                    if (g != 0.f) {
                        int t = g_slot_tok[rr];
                        size_t o = (size_t)t * DDIM + col;
                        atomicAdd(&oout[o],     v0 * g);
                        atomicAdd(&oout[o + 1], v1 * g);
                    }
                } else {
                    size_t o = (size_t)rr * DDIM + col;
                    atomicAdd(&oout[o],     v0);
                    atomicAdd(&oout[o + 1], v1);
                }
            }
        }
    }
}

// ============================================================
// launch — two independent chains:
// s2: zero_out -> split_w -> [evW] -> split_x -> op2 -> op3 -> [evEnd]
// s0: gate -> scan -> scatter -> gather -> (wait evW) -> op0 -> op1 -> (wait evEnd)
// ============================================================
extern "C" void kernel_launch(void* const* d_in, const int* in_sizes, int n_in,
                              void* d_out, int out_size)
{
    const float* x   = (const float*)d_in[0];
    const float* gw  = (const float*)d_in[1];
    const float* w1  = (const float*)d_in[2];
    const float* b1  = (const float*)d_in[3];
    const float* w2  = (const float*)d_in[4];
    const float* b2  = (const float*)d_in[5];
    const float* sw1 = (const float*)d_in[6];
    const float* sb1 = (const float*)d_in[7];
    const float* sw2 = (const float*)d_in[8];
    const float* sb2 = (const float*)d_in[9];
    float* out = (float*)d_out;

    static cudaStream_t s2 = nullptr;
    static cudaEvent_t evFork = nullptr, evW = nullptr, evEnd = nullptr;
    static int attr_done = 0;
    if (!attr_done) {
        cudaFuncSetAttribute(k_mma, cudaFuncAttributeMaxDynamicSharedMemorySize, SMEM_SZ);
        cudaFuncSetAttribute(k_gate, cudaFuncAttributeMaxDynamicSharedMemorySize, GATE_SMEM);
        cudaStreamCreateWithFlags(&s2, cudaStreamNonBlocking);
        cudaEventCreateWithFlags(&evFork, cudaEventDisableTiming);
        cudaEventCreateWithFlags(&evW, cudaEventDisableTiming);
        cudaEventCreateWithFlags(&evEnd, cudaEventDisableTiming);
        attr_done = 1;
    }

    __nv_bfloat16 *w1s, *w2s, *sw1s, *sw2s;
    cudaGetSymbolAddress((void**)&w1s, g_w1s);
    cudaGetSymbolAddress((void**)&w2s, g_w2s);
    cudaGetSymbolAddress((void**)&sw1s, g_sw1s);
    cudaGetSymbolAddress((void**)&sw2s, g_sw2s);

    // fork
    cudaEventRecord(evFork, 0);
    cudaStreamWaitEvent(s2, evFork, 0);

    // ----- branch B (s2): shared-expert chain -----
    k_zero_out<<<(NTOK * (DDIM / 4)) / 256, 256, 0, s2>>>((float4*)out);
    k_split_w<<<(2 * N1 + 2 * N2 + 255) / 256, 256, 0, s2>>>(
        (const float4*)w1, (const float4*)w2, (const float4*)sw1, (const float4*)sw2,
        w1s, w2s, sw1s, sw2s);
    cudaEventRecord(evW, s2);   // w1s/w2s + zeroed out ready
    k_split_x<<<(NTOK * (DDIM / 4)) / 256, 256, 0, s2>>>(x);
    k_mma<<<dim3(16 * (NTOK / 128)), 256, SMEM_SZ, s2>>>(2, 16, sb1, nullptr);   // shared L1
    k_mma<<<dim3(16 * (NTOK / 128)), 256, SMEM_SZ, s2>>>(3, 16, sb2, out);       // shared L2
    cudaEventRecord(evEnd, s2);

    // ----- branch A (s0): routed chain -----
    k_gate<<<NTOK / 8, 256, GATE_SMEM>>>(x, gw);
    k_scan<<<1, 256>>>();
    k_scatter<<<NTOK / 256, 256>>>();
    k_gather<<<NTOK, 256>>>(x);
    cudaStreamWaitEvent(0, evW, 0);
    k_mma<<<dim3(8 * (CAP / 128)), 256, SMEM_SZ>>>(0, 8, b1, nullptr);           // routed L1
    k_mma<<<dim3(16 * (CAP / 128)), 256, SMEM_SZ>>>(1, 16, b2, out);             // routed L2

    // join
    cudaStreamWaitEvent(0, evEnd, 0);
}

// round 17
// speedup vs baseline: 1.0059x; 1.0059x over previous
#include <cuda_runtime.h>
#include <cuda_bf16.h>
#include <math.h>
#include <stdint.h>

// ---------------- problem constants ----------------
#define NTOK 8192
#define DDIM 2048
#define HDIM 1024
#define NEXP 8
#define SHDIM 2048
#define CAP  17408   // 16384 slots + 8*128 pad headroom

#define DH   (DDIM * HDIM)
#define SW   (DDIM * SHDIM)

// phase-1 merged grid: op0 = 136*8 = 1088 blocks, op2 = 64*16 = 1024
#define P1_OP0_BLKS 1088
#define P1_BLKS     2112
// phase-2 merged grid: op3 = 64*16 = 1024 blocks first, op1 = 136*16 = 2176
#define P2_OP3_BLKS 1024
#define P2_BLKS     3200

// ---------------- scratch (device globals) ----------------
__device__ int   g_count[NEXP];
__device__ int   g_cursor[NEXP];
__device__ int   g_pbase[NEXP + 1];
__device__ int   g_tok_eid[NTOK * 2];
__device__ float g_tok_gate[NTOK * 2];
__device__ int   g_tok_slot[NTOK * 2];
__device__ int   g_slot_tok[CAP];
__device__ float g_slot_gate[CAP];

// bf16 hi/lo planes (hi first, lo second)
__device__ __align__(16) __nv_bfloat16 g_A1[2ull * CAP * DDIM];
__device__ __align__(16) __nv_bfloat16 g_xs[2ull * NTOK * DDIM];
__device__ __align__(16) __nv_bfloat16 g_w1s[2ull * NEXP * DH];
__device__ __align__(16) __nv_bfloat16 g_w2s[2ull * NEXP * DH];
__device__ __align__(16) __nv_bfloat16 g_sw1s[2ull * SW];
__device__ __align__(16) __nv_bfloat16 g_sw2s[2ull * SW];
__device__ __align__(16) __nv_bfloat16 g_h[2ull * CAP * HDIM];
__device__ __align__(16) __nv_bfloat16 g_hs[2ull * NTOK * SHDIM];

// ---------------- helpers ----------------
__device__ __forceinline__ uint32_t smem_u32(const void* p) {
    uint32_t a;
    asm("{ .reg .u64 t; cvta.to.shared.u64 t, %1; cvt.u32.u64 %0, t; }" : "=r"(a) : "l"(p));
    return a;
}
__device__ __forceinline__ void cpa16(uint32_t dst, const void* src) {
    asm volatile("cp.async.cg.shared.global [%0], [%1], 16;" :: "r"(dst), "l"(src));
}
#define CP_COMMIT() asm volatile("cp.async.commit_group;" ::: "memory")
#define CP_WAIT1()  asm volatile("cp.async.wait_group 1;" ::: "memory")
#define CP_WAIT0()  asm volatile("cp.async.wait_group 0;" ::: "memory")

__device__ __forceinline__ void ldsm4(uint32_t* r, uint32_t addr) {
    asm volatile("ldmatrix.sync.aligned.m8n8.x4.shared.b16 {%0,%1,%2,%3}, [%4];"
                 : "=r"(r[0]), "=r"(r[1]), "=r"(r[2]), "=r"(r[3]) : "r"(addr));
}
__device__ __forceinline__ void ldsm4t(uint32_t* r, uint32_t addr) {
    asm volatile("ldmatrix.sync.aligned.m8n8.x4.trans.shared.b16 {%0,%1,%2,%3}, [%4];"
                 : "=r"(r[0]), "=r"(r[1]), "=r"(r[2]), "=r"(r[3]) : "r"(addr));
}
__device__ __forceinline__ void mma16816(float* c, const uint32_t* a, const uint32_t* b) {
    asm volatile(
        "mma.sync.aligned.m16n8k16.row.col.f32.bf16.bf16.f32 "
        "{%0,%1,%2,%3}, {%4,%5,%6,%7}, {%8,%9}, {%0,%1,%2,%3};"
        : "+f"(c[0]), "+f"(c[1]), "+f"(c[2]), "+f"(c[3])
        : "r"(a[0]), "r"(a[1]), "r"(a[2]), "r"(a[3]), "r"(b[0]), "r"(b[1]));
}
__device__ __forceinline__ float gelu_exact(float v) {
    return 0.5f * v * (1.0f + erff(v * 0.70710678118654752f));
}
__device__ __forceinline__ uint32_t bf2u(__nv_bfloat16 a, __nv_bfloat16 b) {
    return (uint32_t)__bfloat16_as_ushort(a) | ((uint32_t)__bfloat16_as_ushort(b) << 16);
}
__device__ __forceinline__ void split4(float4 v, uint2& hi, uint2& lo) {
    __nv_bfloat16 h0 = __float2bfloat16(v.x), h1 = __float2bfloat16(v.y);
    __nv_bfloat16 h2 = __float2bfloat16(v.z), h3 = __float2bfloat16(v.w);
    __nv_bfloat16 l0 = __float2bfloat16(v.x - __bfloat162float(h0));
    __nv_bfloat16 l1 = __float2bfloat16(v.y - __bfloat162float(h1));
    __nv_bfloat16 l2 = __float2bfloat16(v.z - __bfloat162float(h2));
    __nv_bfloat16 l3 = __float2bfloat16(v.w - __bfloat162float(h3));
    hi = make_uint2(bf2u(h0, h1), bf2u(h2, h3));
    lo = make_uint2(bf2u(l0, l1), bf2u(l2, l3));
}

// ============================================================
// gating v2: gw staged in padded smem ([d][9] floats, conflict-free),
// one warp per token, 8 tokens per CTA. No global atomics (scan histograms).
// ============================================================
#define GATE_SMEM (DDIM * 9 * 4)

extern __shared__ __align__(16) char smem[];

__global__ void __launch_bounds__(256, 2)
k_gate(const float* __restrict__ x, const float* __restrict__ gw) {
    float* gws = (float*)smem;
    for (int i = threadIdx.x; i < DDIM * 8; i += 256) {
        int d = i >> 3, e = i & 7;
        gws[d * 9 + e] = gw[i];
    }
    __syncthreads();

    int warp = threadIdx.x >> 5, lane = threadIdx.x & 31;
    int tok = blockIdx.x * 8 + warp;
    const float* xr = x + (size_t)tok * DDIM;
    float acc[8] = {0.f,0.f,0.f,0.f,0.f,0.f,0.f,0.f};
    for (int d = lane; d < DDIM; d += 32) {
        float xv = xr[d];
        const float* g = gws + d * 9;
        acc[0] += xv * g[0]; acc[1] += xv * g[1]; acc[2] += xv * g[2]; acc[3] += xv * g[3];
        acc[4] += xv * g[4]; acc[5] += xv * g[5]; acc[6] += xv * g[6]; acc[7] += xv * g[7];
    }
#pragma unroll
    for (int e = 0; e < 8; e++)
#pragma unroll
        for (int o = 16; o; o >>= 1) acc[e] += __shfl_xor_sync(0xffffffffu, acc[e], o);
    if (lane == 0) {
        int e0 = 0; float l0 = acc[0];
#pragma unroll
        for (int e = 1; e < 8; e++) if (acc[e] > l0) { l0 = acc[e]; e0 = e; }
        int e1 = -1; float l1 = -3.4e38f;
#pragma unroll
        for (int e = 0; e < 8; e++) if (e != e0 && acc[e] > l1) { l1 = acc[e]; e1 = e; }
        float ex = expf(l1 - l0);
        float inv = 1.f / (1.f + ex);
        g_tok_eid[tok*2+0] = e0;  g_tok_eid[tok*2+1] = e1;
        g_tok_gate[tok*2+0] = inv; g_tok_gate[tok*2+1] = ex * inv;
    }
}

// zero the output buffer (atomic accumulation target)
__global__ void k_zero_out(float4* __restrict__ out) {
    size_t i = (size_t)blockIdx.x * 256 + threadIdx.x;
    out[i] = make_float4(0.f, 0.f, 0.f, 0.f);
}

// scan: histogram from g_tok_eid, bases, cursors, parallel pad fill
__global__ void k_scan() {
    __shared__ int cnt[NEXP];
    __shared__ int sbase[NEXP + 1];
    if (threadIdx.x < NEXP) cnt[threadIdx.x] = 0;
    __syncthreads();
    for (int i = threadIdx.x; i < NTOK * 2; i += 256)
        atomicAdd(&cnt[g_tok_eid[i]], 1);
    __syncthreads();
    if (threadIdx.x == 0) {
        int base = 0;
        for (int e = 0; e < NEXP; e++) {
            g_count[e] = cnt[e];
            g_pbase[e] = base; g_cursor[e] = base; sbase[e] = base;
            base += (cnt[e] + 127) & ~127;
        }
        g_pbase[NEXP] = base; sbase[NEXP] = base;
    }
    __syncthreads();
    for (int e = 0; e < NEXP; e++) {
        int cs = sbase[e] + cnt[e];
        int ce = sbase[e + 1];
        for (int s = cs + threadIdx.x; s < ce; s += blockDim.x) {
            g_slot_tok[s] = 0; g_slot_gate[s] = 0.f;
        }
    }
}

__global__ void k_scatter() {
    int tok = blockIdx.x * 256 + threadIdx.x;
#pragma unroll
    for (int k = 0; k < 2; k++) {
        int e = g_tok_eid[tok*2+k];
        int pos = atomicAdd(&g_cursor[e], 1);
        g_slot_tok[pos] = tok;
        g_slot_gate[pos] = g_tok_gate[tok*2+k];
        g_tok_slot[tok*2+k] = pos;
    }
}

#define N1 (NEXP * DH / 4)
#define N2 (SW / 4)
__global__ void k_split_w(const float4* __restrict__ w1, const float4* __restrict__ w2,
                          const float4* __restrict__ sw1, const float4* __restrict__ sw2,
                          __nv_bfloat16* __restrict__ w1s, __nv_bfloat16* __restrict__ w2s,
                          __nv_bfloat16* __restrict__ sw1s, __nv_bfloat16* __restrict__ sw2s) {
    long long i = (long long)blockIdx.x * 256 + threadIdx.x;
    const float4* src; __nv_bfloat16 *dh, *dl; long long j;
    if (i < N1)                { j = i;               src = w1;  dh = w1s;  dl = w1s  + (size_t)NEXP * DH; }
    else if (i < 2LL * N1)     { j = i - N1;          src = w2;  dh = w2s;  dl = w2s  + (size_t)NEXP * DH; }
    else if (i < 2LL*N1 + N2)  { j = i - 2LL*N1;      src = sw1; dh = sw1s; dl = sw1s + (size_t)SW; }
    else                       { j = i - 2LL*N1 - N2; src = sw2; dh = sw2s; dl = sw2s + (size_t)SW; }
    uint2 hi, lo; split4(src[j], hi, lo);
    *(uint2*)(dh + j * 4) = hi;
    *(uint2*)(dl + j * 4) = lo;
}

__global__ void k_split_x_gather(const float* __restrict__ x) {
    int tok = blockIdx.x;
    int s0 = g_tok_slot[tok * 2], s1 = g_tok_slot[tok * 2 + 1];
    const float4* src = (const float4*)(x + (size_t)tok * DDIM);
#pragma unroll
    for (int i = 0; i < 2; i++) {
        int idx = threadIdx.x + i * 256;
        uint2 hi, lo; split4(src[idx], hi, lo);
        size_t oT = (size_t)tok * DDIM + idx * 4;
        *(uint2*)(g_xs + oT) = hi;
        *(uint2*)(g_xs + (size_t)NTOK * DDIM + oT) = lo;
        size_t o0 = (size_t)s0 * DDIM + idx * 4;
        size_t o1 = (size_t)s1 * DDIM + idx * 4;
        *(uint2*)(g_A1 + o0) = hi;
        *(uint2*)(g_A1 + (size_t)CAP * DDIM + o0) = lo;
        *(uint2*)(g_A1 + o1) = hi;
        *(uint2*)(g_A1 + (size_t)CAP * DDIM + o1) = lo;
    }
}

// ============================================================
// HMMA GEMM (identical to the 1915.8us kernel)
// ============================================================
#define OAH 0
#define OAL 10240
#define OBH 20480
#define OBL 29184
#define STG 37888
#define SMEM_SZ (3 * STG)

template<int PHASE>
__global__ void __launch_bounds__(256, 2)
k_mma(const float* __restrict__ biasA, const float* __restrict__ biasB,
      float* __restrict__ oout)
{
    const int tid = threadIdx.x, wid = tid >> 5, lane = tid & 31;
    const int bid = blockIdx.x;

    int op, mb, nb;
    if (PHASE == 1) {
        if (bid < P1_OP0_BLKS) { op = 0; mb = bid >> 3;  nb = bid & 7; }
        else { int t = bid - P1_OP0_BLKS; op = 2; mb = t >> 4; nb = t & 15; }
    } else {
        if (bid < P2_OP3_BLKS) { op = 3; mb = bid >> 4; nb = bid & 15; }
        else { int t = bid - P2_OP3_BLKS; op = 1; mb = t >> 4; nb = t & 15; }
    }
    const int row_base = mb * 128;
    const int n0 = nb * 128;

    int K, ldA, ldB, ldO;
    const float* bias;
    int e = 0;
    if (op == 0 || op == 1) {
        if (row_base >= g_pbase[NEXP]) return;
        while (row_base >= g_pbase[e + 1]) e++;
    }
    const __nv_bfloat16 *Agh, *Agl, *Bgh, *Bgl;
    if (op == 0)      { K = DDIM; ldA = DDIM; ldB = HDIM; ldO = HDIM; bias = biasA + (size_t)e * HDIM;
                        Agh = g_A1;  Agl = Agh + (size_t)CAP * DDIM;
                        Bgh = g_w1s + (size_t)e * DH; Bgl = Bgh + (size_t)NEXP * DH; }
    else if (op == 1) { K = HDIM; ldA = HDIM; ldB = DDIM; ldO = DDIM; bias = biasB + (size_t)e * DDIM;
                        Agh = g_h;   Agl = Agh + (size_t)CAP * HDIM;
                        Bgh = g_w2s + (size_t)e * DH; Bgl = Bgh + (size_t)NEXP * DH; }
    else if (op == 2) { K = DDIM; ldA = DDIM; ldB = SHDIM; ldO = SHDIM; bias = biasB;
                        Agh = g_xs;  Agl = Agh + (size_t)NTOK * DDIM;
                        Bgh = g_sw1s; Bgl = Bgh + (size_t)SW; }
    else              { K = SHDIM; ldA = SHDIM; ldB = DDIM; ldO = DDIM; bias = biasA;
                        Agh = g_hs;  Agl = Agh + (size_t)NTOK * SHDIM;
                        Bgh = g_sw2s; Bgl = Bgh + (size_t)SW; }
    Agh += (size_t)row_base * ldA;
    Agl += (size_t)row_base * ldA;

    const uint32_t sb = smem_u32(smem);

    const int ar = tid >> 2, ac = (tid & 3) * 8;
    const int br = tid >> 4, bc = (tid & 15) * 8;

    auto load_stage = [&](int c, int st) {
        int kc = c << 5;
        uint32_t stb = sb + st * STG;
#pragma unroll
        for (int i = 0; i < 2; i++) {
            int row = ar + i * 64;
            uint32_t d = stb + (row * 40 + ac) * 2;
            cpa16(d + OAH, Agh + (size_t)row * ldA + kc + ac);
            cpa16(d + OAL, Agl + (size_t)row * ldA + kc + ac);
        }
#pragma unroll
        for (int i = 0; i < 2; i++) {
            int row = br + i * 16;
            uint32_t d = stb + (row * 136 + bc) * 2;
            cpa16(d + OBH, Bgh + (size_t)(kc + row) * ldB + n0 + bc);
            cpa16(d + OBL, Bgl + (size_t)(kc + row) * ldB + n0 + bc);
        }
        CP_COMMIT();
    };

    const int wm = (wid >> 2) * 64;
    const int wn = (wid & 3) * 32;
    const int lm = lane & 15, lh = lane >> 4;

    float acc[4][4][4] = {};

    const int nc = K >> 5;
    load_stage(0, 0);
    load_stage(1, 1);
    int st = 0;
    for (int c = 0; c < nc; c++) {
        if (c == nc - 1) { CP_WAIT0(); } else { CP_WAIT1(); }
        __syncthreads();

        uint32_t aAh = sb + st * STG + OAH;
        uint32_t aAl = sb + st * STG + OAL;
        uint32_t aBh = sb + st * STG + OBH;
        uint32_t aBl = sb + st * STG + OBL;
#pragma unroll
        for (int ks = 0; ks < 2; ks++) {
            int k0 = ks * 16;
            uint32_t af[4][4], bf[2][4], bf2[2][4];
#pragma unroll
            for (int mi = 0; mi < 4; mi++)
                ldsm4(af[mi], aAh + ((wm + mi * 16 + lm) * 40 + k0 + lh * 8) * 2);
#pragma unroll
            for (int np = 0; np < 2; np++)
                ldsm4t(bf[np], aBh + ((k0 + lm) * 136 + wn + np * 16 + lh * 8) * 2);
#pragma unroll
            for (int mi = 0; mi < 4; mi++)
#pragma unroll
                for (int ni = 0; ni < 4; ni++)
                    mma16816(acc[mi][ni], af[mi], &bf[ni >> 1][(ni & 1) * 2]);
#pragma unroll
            for (int np = 0; np < 2; np++)
                ldsm4t(bf2[np], aBl + ((k0 + lm) * 136 + wn + np * 16 + lh * 8) * 2);
#pragma unroll
            for (int mi = 0; mi < 4; mi++)
#pragma unroll
                for (int ni = 0; ni < 4; ni++)
                    mma16816(acc[mi][ni], af[mi], &bf2[ni >> 1][(ni & 1) * 2]);
#pragma unroll
            for (int mi = 0; mi < 4; mi++)
                ldsm4(af[mi], aAl + ((wm + mi * 16 + lm) * 40 + k0 + lh * 8) * 2);
#pragma unroll
            for (int mi = 0; mi < 4; mi++)
#pragma unroll
                for (int ni = 0; ni < 4; ni++)
                    mma16816(acc[mi][ni], af[mi], &bf[ni >> 1][(ni & 1) * 2]);
        }
        if (c + 2 < nc) load_stage(c + 2, st == 0 ? 2 : st - 1);
        st = (st == 2) ? 0 : st + 1;
    }

    // ---------------- epilogue ----------------
    __nv_bfloat16 *obh = 0, *obl = 0;
    if (op == 0)      { obh = g_h;  obl = g_h  + (size_t)CAP * HDIM; }
    else if (op == 2) { obh = g_hs; obl = g_hs + (size_t)NTOK * SHDIM; }

#pragma unroll
    for (int mi = 0; mi < 4; mi++) {
#pragma unroll
        for (int ni = 0; ni < 4; ni++) {
            int r = row_base + wm + mi * 16 + (lane >> 2);
            int col = n0 + wn + ni * 8 + (lane & 3) * 2;
            float b0 = bias[col], b1 = bias[col + 1];
#pragma unroll
            for (int half = 0; half < 2; half++) {
                int rr = r + half * 8;
                float v0 = acc[mi][ni][half * 2 + 0] + b0;
                float v1 = acc[mi][ni][half * 2 + 1] + b1;
                if (op == 0 || op == 2) {
                    size_t o = (size_t)rr * ldO + col;
                    v0 = gelu_exact(v0); v1 = gelu_exact(v1);
                    __nv_bfloat16 h0 = __float2bfloat16(v0);
                    __nv_bfloat16 h1 = __float2bfloat16(v1);
                    __nv_bfloat16 l0 = __float2bfloat16(v0 - __bfloat162float(h0));
                    __nv_bfloat16 l1 = __float2bfloat16(v1 - __bfloat162float(h1));
                    *(uint32_t*)(obh + o) = bf2u(h0, h1);
                    *(uint32_t*)(obl + o) = bf2u(l0, l1);
                } else if (op == 1) {
                    float g = g_slot_gate[rr];
                    if (g != 0.f) {
                        int t = g_slot_tok[rr];
                        size_t o = (size_t)t * DDIM + col;
                        atomicAdd(&oout[o],     v0 * g);
                        atomicAdd(&oout[o + 1], v1 * g);
                    }
                } else {
                    size_t o = (size_t)rr * DDIM + col;
                    atomicAdd(&oout[o],     v0);
                    atomicAdd(&oout[o + 1], v1);
                }
            }
        }
    }
}

// ============================================================
// launch — fork/join two-branch graph (R15 structure)
// ============================================================
extern "C" void kernel_launch(void* const* d_in, const int* in_sizes, int n_in,
                              void* d_out, int out_size)
{
    const float* x   = (const float*)d_in[0];
    const float* gw  = (const float*)d_in[1];
    const float* w1  = (const float*)d_in[2];
    const float* b1  = (const float*)d_in[3];
    const float* w2  = (const float*)d_in[4];
    const float* b2  = (const float*)d_in[5];
    const float* sw1 = (const float*)d_in[6];
    const float* sb1 = (const float*)d_in[7];
    const float* sw2 = (const float*)d_in[8];
    const float* sb2 = (const float*)d_in[9];
    float* out = (float*)d_out;

    static cudaStream_t s2 = nullptr;
    static cudaEvent_t evFork = nullptr, evJoin = nullptr;
    static int attr_done = 0;
    if (!attr_done) {
        cudaFuncSetAttribute(k_mma<1>, cudaFuncAttributeMaxDynamicSharedMemorySize, SMEM_SZ);
        cudaFuncSetAttribute(k_mma<2>, cudaFuncAttributeMaxDynamicSharedMemorySize, SMEM_SZ);
        cudaFuncSetAttribute(k_gate, cudaFuncAttributeMaxDynamicSharedMemorySize, GATE_SMEM);
        cudaStreamCreateWithFlags(&s2, cudaStreamNonBlocking);
        cudaEventCreateWithFlags(&evFork, cudaEventDisableTiming);
        cudaEventCreateWithFlags(&evJoin, cudaEventDisableTiming);
        attr_done = 1;
    }

    __nv_bfloat16 *w1s, *w2s, *sw1s, *sw2s;
    cudaGetSymbolAddress((void**)&w1s, g_w1s);
    cudaGetSymbolAddress((void**)&w2s, g_w2s);
    cudaGetSymbolAddress((void**)&sw1s, g_sw1s);
    cudaGetSymbolAddress((void**)&sw2s, g_sw2s);

    // fork: branch B on s2 (input-only work)
    cudaEventRecord(evFork, 0);
    cudaStreamWaitEvent(s2, evFork, 0);
    k_zero_out<<<(NTOK * (DDIM / 4)) / 256, 256, 0, s2>>>((float4*)out);
    k_split_w<<<(2 * N1 + 2 * N2 + 255) / 256, 256, 0, s2>>>(
        (const float4*)w1, (const float4*)w2, (const float4*)sw1, (const float4*)sw2,
        w1s, w2s, sw1s, sw2s);
    cudaEventRecord(evJoin, s2);

    // branch A on stream 0: gating chain
    k_gate<<<NTOK / 8, 256, GATE_SMEM>>>(x, gw);
    k_scan<<<1, 256>>>();
    k_scatter<<<NTOK / 256, 256>>>();
    k_split_x_gather<<<NTOK, 256>>>(x);

    // join, then GEMM phases
    cudaStreamWaitEvent(0, evJoin, 0);
    k_mma<1><<<P1_BLKS, 256, SMEM_SZ>>>(b1, sb1, nullptr);
    k_mma<2><<<P2_BLKS, 256, SMEM_SZ>>>(sb2, b2, out);
}